// round 5
// baseline (speedup 1.0000x reference)
#include <cuda_runtime.h>
#include <cuda_bf16.h>
#include <math.h>
#include <stdint.h>

// Problem constants
#define Bq  2
#define Sq  2048
#define Dm  1024
#define Hh  16
#define HDc 64
#define Mtot (Bq*Sq)   // 4096

// ---------------- device scratch ----------------
__device__ __nv_bfloat16 g_Xh[Mtot*Dm];    // x split hi/lo, [M][K]
__device__ __nv_bfloat16 g_Xl[Mtot*Dm];
__device__ __nv_bfloat16 g_Wh[4][Dm*Dm];   // W^T split hi/lo, [N][K]
__device__ __nv_bfloat16 g_Wl[4][Dm*Dm];
// split Q/K/V in (B,H,S,HD), Q pre-scaled by 0.125
__device__ __nv_bfloat16 g_Qh[Mtot*Dm], g_Ql[Mtot*Dm];
__device__ __nv_bfloat16 g_Kh[Mtot*Dm], g_Kl[Mtot*Dm];
__device__ __nv_bfloat16 g_Vh[Mtot*Dm], g_Vl[Mtot*Dm];
// attention out split, [M][Dm]
__device__ __nv_bfloat16 g_AH[Mtot*Dm], g_AL[Mtot*Dm];

// ---------------- helpers ----------------
__device__ __forceinline__ uint32_t smem_u32(const void* p) {
    uint32_t a;
    asm("{ .reg .u64 t; cvta.to.shared.u64 t, %1; cvt.u32.u64 %0, t; }" : "=r"(a) : "l"(p));
    return a;
}
__device__ __forceinline__ void cp16(uint32_t saddr, const void* gptr) {
    asm volatile("cp.async.cg.shared.global [%0], [%1], 16;" :: "r"(saddr), "l"(gptr) : "memory");
}
__device__ __forceinline__ void cp_commit() {
    asm volatile("cp.async.commit_group;" ::: "memory");
}
__device__ __forceinline__ void cp_wait0() {
    asm volatile("cp.async.wait_group 0;" ::: "memory");
}
__device__ __forceinline__ void ldsm_x4(uint32_t* r, uint32_t a) {
    asm volatile("ldmatrix.sync.aligned.m8n8.x4.shared.b16 {%0,%1,%2,%3}, [%4];"
                 : "=r"(r[0]), "=r"(r[1]), "=r"(r[2]), "=r"(r[3]) : "r"(a));
}
__device__ __forceinline__ void ldsm_x2(uint32_t* r, uint32_t a) {
    asm volatile("ldmatrix.sync.aligned.m8n8.x2.shared.b16 {%0,%1}, [%2];"
                 : "=r"(r[0]), "=r"(r[1]) : "r"(a));
}
__device__ __forceinline__ void ldsm_x2t(uint32_t* r, uint32_t a) {
    asm volatile("ldmatrix.sync.aligned.m8n8.x2.trans.shared.b16 {%0,%1}, [%2];"
                 : "=r"(r[0]), "=r"(r[1]) : "r"(a));
}
__device__ __forceinline__ void mma16816(float* c, const uint32_t* a, const uint32_t* b) {
    asm volatile(
        "mma.sync.aligned.m16n8k16.row.col.f32.bf16.bf16.f32 "
        "{%0,%1,%2,%3}, {%4,%5,%6,%7}, {%8,%9}, {%0,%1,%2,%3};"
        : "+f"(c[0]), "+f"(c[1]), "+f"(c[2]), "+f"(c[3])
        : "r"(a[0]), "r"(a[1]), "r"(a[2]), "r"(a[3]), "r"(b[0]), "r"(b[1]));
}
__device__ __forceinline__ uint32_t pack_split(float a, float b, uint32_t& lo) {
    __nv_bfloat16 ha = __float2bfloat16(a), hb = __float2bfloat16(b);
    __nv_bfloat16 la = __float2bfloat16(a - __bfloat162float(ha));
    __nv_bfloat16 lb = __float2bfloat16(b - __bfloat162float(hb));
    uint16_t uha = *(uint16_t*)&ha, uhb = *(uint16_t*)&hb;
    uint16_t ula = *(uint16_t*)&la, ulb = *(uint16_t*)&lb;
    lo = (uint32_t)ula | ((uint32_t)ulb << 16);
    return (uint32_t)uha | ((uint32_t)uhb << 16);
}

// ---------------------------------------------------------------------------
// split-bf16 conversion kernels
// ---------------------------------------------------------------------------
__global__ __launch_bounds__(256) void convx_k(const float* __restrict__ X,
                                               __nv_bfloat16* __restrict__ H,
                                               __nv_bfloat16* __restrict__ L)
{
    int i = blockIdx.x * blockDim.x + threadIdx.x;
    float4 v = ((const float4*)X)[i];
    uint32_t l0, l1;
    uint32_t h0 = pack_split(v.x, v.y, l0);
    uint32_t h1 = pack_split(v.z, v.w, l1);
    ((uint2*)H)[i] = make_uint2(h0, h1);
    ((uint2*)L)[i] = make_uint2(l0, l1);
}

__global__ __launch_bounds__(256) void convw_k(const float* __restrict__ W,
                                               __nv_bfloat16* __restrict__ Th,
                                               __nv_bfloat16* __restrict__ Tl)
{
    __shared__ float t[32][33];
    int n0 = blockIdx.x * 32, k0 = blockIdx.y * 32;
    int tx = threadIdx.x, ty = threadIdx.y;
    #pragma unroll
    for (int j = ty; j < 32; j += 8)
        t[j][tx] = W[(size_t)(k0 + j) * Dm + n0 + tx];
    __syncthreads();
    #pragma unroll
    for (int j = ty; j < 32; j += 8) {
        float v = t[tx][j];
        __nv_bfloat16 h = __float2bfloat16(v);
        float l = v - __bfloat162float(h);
        size_t o = (size_t)(n0 + j) * Dm + k0 + tx;
        Th[o] = h;
        Tl[o] = __float2bfloat16(l);
    }
}

// ---------------------------------------------------------------------------
// Shared GEMM mainloop pieces (CTA 128x128, BK=32, 8 warps)
// ---------------------------------------------------------------------------
#define GP 40
#define MATB (128*GP*2)
#define STAGEB (4*MATB)

#define GEMM_MAINLOOP(gAh, gAl, gBh, gBl)                                         \
    float acc[4][4][4];                                                           \
    _Pragma("unroll") for (int t = 0; t < 4; t++)                                 \
        _Pragma("unroll") for (int j = 0; j < 4; j++)                             \
            _Pragma("unroll") for (int e = 0; e < 4; e++) acc[t][j][e] = 0.f;     \
    const int r0 = tid >> 2, c0 = tid & 3;                                        \
    const int r1 = (tid + 256) >> 2, c1 = (tid + 256) & 3;                        \
    auto issue = [&](int kt, int buf) {                                           \
        const int kc = kt * 32;                                                   \
        const uint32_t base = sb + buf * STAGEB;                                  \
        {                                                                         \
            uint32_t so = (uint32_t)(r0 * (GP*2) + c0 * 16);                      \
            size_t  go = (size_t)r0 * Dm + kc + c0 * 8;                           \
            cp16(base + 0*MATB + so, gAh + go);                                   \
            cp16(base + 1*MATB + so, gAl + go);                                   \
            cp16(base + 2*MATB + so, gBh + go);                                   \
            cp16(base + 3*MATB + so, gBl + go);                                   \
        }                                                                         \
        {                                                                         \
            uint32_t so = (uint32_t)(r1 * (GP*2) + c1 * 16);                      \
            size_t  go = (size_t)r1 * Dm + kc + c1 * 8;                           \
            cp16(base + 0*MATB + so, gAh + go);                                   \
            cp16(base + 1*MATB + so, gAl + go);                                   \
            cp16(base + 2*MATB + so, gBh + go);                                   \
            cp16(base + 3*MATB + so, gBl + go);                                   \
        }                                                                         \
        cp_commit();                                                              \
    };                                                                            \
    const int aRow = wr * 64 + (lane & 15);                                       \
    const int aKh  = (lane >> 4) * 8;                                             \
    const int bRowL = wc * 32 + (lane & 7);                                       \
    const int bKh   = ((lane >> 3) & 1) * 8;                                      \
    issue(0, 0);                                                                  \
    for (int kt = 0; kt < 32; kt++) {                                             \
        cp_wait0();                                                               \
        __syncthreads();                                                          \
        if (kt + 1 < 32) issue(kt + 1, (kt + 1) & 1);                             \
        const uint32_t base = sb + (kt & 1) * STAGEB;                             \
        _Pragma("unroll") for (int kk = 0; kk < 2; kk++) {                        \
            uint32_t bh[4][2], bl[4][2];                                          \
            _Pragma("unroll") for (int j = 0; j < 4; j++) {                       \
                uint32_t ba = base + 2*MATB +                                     \
                    (uint32_t)(((bRowL + j * 8) * GP + kk * 16 + bKh) * 2);       \
                ldsm_x2(bh[j], ba);                                               \
                ldsm_x2(bl[j], ba + MATB);                                        \
            }                                                                     \
            _Pragma("unroll") for (int t = 0; t < 4; t++) {                       \
                uint32_t aa = base +                                              \
                    (uint32_t)(((aRow + t * 16) * GP + kk * 16 + aKh) * 2);       \
                uint32_t ah[4], al[4];                                            \
                ldsm_x4(ah, aa);                                                  \
                ldsm_x4(al, aa + MATB);                                           \
                _Pragma("unroll") for (int j = 0; j < 4; j++) {                   \
                    mma16816(acc[t][j], ah, bh[j]);                               \
                    mma16816(acc[t][j], ah, bl[j]);                               \
                    mma16816(acc[t][j], al, bh[j]);                               \
                }                                                                 \
            }                                                                     \
        }                                                                         \
        __syncthreads();                                                          \
    }

// Fused QKV projection: C[4096][3072] = X @ [WQ|WK|WV]^T, split-bf16 out.
__global__ __launch_bounds__(256) void qkv_gemm(
    const __nv_bfloat16* __restrict__ Agh, const __nv_bfloat16* __restrict__ Agl,
    const __nv_bfloat16* __restrict__ Bgh, const __nv_bfloat16* __restrict__ Bgl,
    __nv_bfloat16* __restrict__ Qh, __nv_bfloat16* __restrict__ Ql,
    __nv_bfloat16* __restrict__ Kh, __nv_bfloat16* __restrict__ Kl,
    __nv_bfloat16* __restrict__ Vh, __nv_bfloat16* __restrict__ Vl)
{
    extern __shared__ char smc[];
    const uint32_t sb = smem_u32(smc);
    const int tid = threadIdx.x, lane = tid & 31, w = tid >> 5;
    const int wr = w >> 2, wc = w & 3;
    const int rowBase = blockIdx.y * 128, colBase = blockIdx.x * 128;

    const __nv_bfloat16* gAh = Agh + (size_t)rowBase * Dm;
    const __nv_bfloat16* gAl = Agl + (size_t)rowBase * Dm;
    const __nv_bfloat16* gBh = Bgh + (size_t)colBase * Dm;
    const __nv_bfloat16* gBl = Bgl + (size_t)colBase * Dm;

    GEMM_MAINLOOP(gAh, gAl, gBh, gBl)

    const int er = lane >> 2, ec = (lane & 3) * 2;
    const int which = colBase >> 10;            // 0=Q 1=K 2=V (128-block within one)
    __nv_bfloat16* dh = which == 0 ? Qh : (which == 1 ? Kh : Vh);
    __nv_bfloat16* dl = which == 0 ? Ql : (which == 1 ? Kl : Vl);
    const float scale = which == 0 ? 0.125f : 1.0f;
    #pragma unroll
    for (int t = 0; t < 4; t++) {
        #pragma unroll
        for (int j = 0; j < 4; j++) {
            int m0 = rowBase + wr * 64 + t * 16 + er;
            int n  = (colBase & 1023) + wc * 32 + j * 8 + ec;
            int h = n >> 6, hd = n & 63;
            #pragma unroll
            for (int half = 0; half < 2; half++) {
                int m = m0 + half * 8;
                int b = m >> 11, s = m & 2047;
                uint32_t lo;
                uint32_t hi = pack_split(acc[t][j][2*half] * scale,
                                         acc[t][j][2*half+1] * scale, lo);
                size_t o = ((size_t)((b * Hh + h) * Sq + s)) * HDc + hd;
                *(uint32_t*)&dh[o] = hi;
                *(uint32_t*)&dl[o] = lo;
            }
        }
    }
}

// Output projection: C[4096][1024] fp32 = AH/AL @ WO^T
__global__ __launch_bounds__(256) void wo_gemm(
    const __nv_bfloat16* __restrict__ Agh, const __nv_bfloat16* __restrict__ Agl,
    const __nv_bfloat16* __restrict__ Bgh, const __nv_bfloat16* __restrict__ Bgl,
    float* __restrict__ dst)
{
    extern __shared__ char smc[];
    const uint32_t sb = smem_u32(smc);
    const int tid = threadIdx.x, lane = tid & 31, w = tid >> 5;
    const int wr = w >> 2, wc = w & 3;
    const int rowBase = blockIdx.y * 128, colBase = blockIdx.x * 128;

    const __nv_bfloat16* gAh = Agh + (size_t)rowBase * Dm;
    const __nv_bfloat16* gAl = Agl + (size_t)rowBase * Dm;
    const __nv_bfloat16* gBh = Bgh + (size_t)colBase * Dm;
    const __nv_bfloat16* gBl = Bgl + (size_t)colBase * Dm;

    GEMM_MAINLOOP(gAh, gAl, gBh, gBl)

    const int er = lane >> 2, ec = (lane & 3) * 2;
    #pragma unroll
    for (int t = 0; t < 4; t++) {
        #pragma unroll
        for (int j = 0; j < 4; j++) {
            int m0 = rowBase + wr * 64 + t * 16 + er;
            int n  = colBase + wc * 32 + j * 8 + ec;
            *(float2*)&dst[(size_t)m0 * Dm + n] = make_float2(acc[t][j][0], acc[t][j][1]);
            *(float2*)&dst[(size_t)(m0 + 8) * Dm + n] = make_float2(acc[t][j][2], acc[t][j][3]);
        }
    }
}

// ---------------------------------------------------------------------------
// HMMA flash attention, bf16 split inputs, cp.async double-buffered K/V.
// CTA: 64 q-rows, 4 warps. Output: split bf16 AH/AL.
// ---------------------------------------------------------------------------
#define AP 72
#define ATB (64*AP*2)     // 9216 bytes per tile
#define QB  (2*ATB)       // Q hi+lo
#define STG (4*ATB)       // Kh,Kl,Vh,Vl per stage

__global__ __launch_bounds__(128) void attn_mma(
    const __nv_bfloat16* __restrict__ Qhg, const __nv_bfloat16* __restrict__ Qlg,
    const __nv_bfloat16* __restrict__ Khg, const __nv_bfloat16* __restrict__ Klg,
    const __nv_bfloat16* __restrict__ Vhg, const __nv_bfloat16* __restrict__ Vlg,
    __nv_bfloat16* __restrict__ AH, __nv_bfloat16* __restrict__ AL)
{
    extern __shared__ char smc[];
    const uint32_t sb = smem_u32(smc);
    const uint32_t sQh = sb, sQl = sb + ATB;

    const int tid = threadIdx.x, lane = tid & 31, w = tid >> 5;
    const int q0 = ((int)gridDim.x - 1 - (int)blockIdx.x) * 64;   // longest-first
    const int h  = blockIdx.y;
    const int b  = blockIdx.z;

    const size_t hb = (size_t)((b * Hh + h) * Sq) * HDc;
    const __nv_bfloat16* Qhb = Qhg + hb;
    const __nv_bfloat16* Qlb = Qlg + hb;
    const __nv_bfloat16* Khb = Khg + hb;
    const __nv_bfloat16* Klb = Klg + hb;
    const __nv_bfloat16* Vhb = Vhg + hb;
    const __nv_bfloat16* Vlb = Vlg + hb;

    // Q tile: 64x64 bf16 hi/lo (already scaled)
    for (int i = tid; i < 512; i += 128) {
        int r = i >> 3, c = (i & 7) * 8;
        uint32_t off = (uint32_t)(r * AP + c) * 2;
        *(uint4*)(smc + off)       = *(const uint4*)&Qhb[(size_t)(q0 + r) * HDc + c];
        *(uint4*)(smc + ATB + off) = *(const uint4*)&Qlb[(size_t)(q0 + r) * HDc + c];
    }

    const int nTiles = q0 / 64 + 1;

    auto issue = [&](int kt, int st) {
        const uint32_t base = sb + QB + st * STG;
        #pragma unroll
        for (int p = 0; p < 4; p++) {
            int i = tid + p * 128;
            int r = i >> 3, c = (i & 7) * 8;
            uint32_t so = (uint32_t)(r * AP + c) * 2;
            size_t go = (size_t)(kt * 64 + r) * HDc + c;
            cp16(base + 0*ATB + so, Khb + go);
            cp16(base + 1*ATB + so, Klb + go);
            cp16(base + 2*ATB + so, Vhb + go);
            cp16(base + 3*ATB + so, Vlb + go);
        }
        cp_commit();
    };

    float m0 = -INFINITY, m1 = -INFINITY, l0s = 0.f, l1s = 0.f;
    float o[8][4];
    #pragma unroll
    for (int j = 0; j < 8; j++)
        #pragma unroll
        for (int e = 0; e < 4; e++) o[j][e] = 0.f;

    const int er = lane >> 2, ec = (lane & 3) * 2;

    issue(0, 0);

    for (int kt = 0; kt < nTiles; kt++) {
        cp_wait0();
        __syncthreads();
        if (kt + 1 < nTiles) issue(kt + 1, (kt + 1) & 1);

        const uint32_t base = sb + QB + (kt & 1) * STG;
        const uint32_t sKh = base, sKl = base + ATB, sVh = base + 2*ATB, sVl = base + 3*ATB;

        // S = Q K^T
        float s[8][4];
        #pragma unroll
        for (int j = 0; j < 8; j++)
            #pragma unroll
            for (int e = 0; e < 4; e++) s[j][e] = 0.f;

        #pragma unroll
        for (int ks = 0; ks < 4; ks++) {
            uint32_t aoff = (uint32_t)(((w * 16 + (lane & 15)) * AP + ks * 16 + (lane >> 4) * 8) * 2);
            uint32_t ah[4], al[4];
            ldsm_x4(ah, sQh + aoff);
            ldsm_x4(al, sQl + aoff);
            #pragma unroll
            for (int j = 0; j < 8; j++) {
                uint32_t boff = (uint32_t)(((j * 8 + (lane & 7)) * AP + ks * 16 + ((lane >> 3) & 1) * 8) * 2);
                uint32_t bh[2], bl[2];
                ldsm_x2(bh, sKh + boff);
                ldsm_x2(bl, sKl + boff);
                mma16816(s[j], ah, bh);
                mma16816(s[j], ah, bl);
                mma16816(s[j], al, bh);
            }
        }

        const int row0 = q0 + w * 16 + er, row1 = row0 + 8;
        if (kt == nTiles - 1) {
            #pragma unroll
            for (int j = 0; j < 8; j++) {
                int k = q0 + j * 8 + ec;
                if (k     > row0) s[j][0] = -INFINITY;
                if (k + 1 > row0) s[j][1] = -INFINITY;
                if (k     > row1) s[j][2] = -INFINITY;
                if (k + 1 > row1) s[j][3] = -INFINITY;
            }
        }

        float rm0 = -INFINITY, rm1 = -INFINITY;
        #pragma unroll
        for (int j = 0; j < 8; j++) {
            rm0 = fmaxf(rm0, fmaxf(s[j][0], s[j][1]));
            rm1 = fmaxf(rm1, fmaxf(s[j][2], s[j][3]));
        }
        rm0 = fmaxf(rm0, __shfl_xor_sync(0xffffffffu, rm0, 1));
        rm0 = fmaxf(rm0, __shfl_xor_sync(0xffffffffu, rm0, 2));
        rm1 = fmaxf(rm1, __shfl_xor_sync(0xffffffffu, rm1, 1));
        rm1 = fmaxf(rm1, __shfl_xor_sync(0xffffffffu, rm1, 2));
        float mn0 = fmaxf(m0, rm0), mn1 = fmaxf(m1, rm1);
        float c0 = __expf(m0 - mn0), c1 = __expf(m1 - mn1);
        m0 = mn0; m1 = mn1;

        float la0 = 0.f, la1 = 0.f;
        #pragma unroll
        for (int j = 0; j < 8; j++) {
            s[j][0] = __expf(s[j][0] - m0);
            s[j][1] = __expf(s[j][1] - m0);
            s[j][2] = __expf(s[j][2] - m1);
            s[j][3] = __expf(s[j][3] - m1);
            la0 += s[j][0] + s[j][1];
            la1 += s[j][2] + s[j][3];
            o[j][0] *= c0; o[j][1] *= c0;
            o[j][2] *= c1; o[j][3] *= c1;
        }
        l0s = l0s * c0 + la0;
        l1s = l1s * c1 + la1;

        // O += P @ V
        #pragma unroll
        for (int aj = 0; aj < 4; aj++) {
            uint32_t ph[4], pl[4];
            ph[0] = pack_split(s[2*aj][0],   s[2*aj][1],   pl[0]);
            ph[1] = pack_split(s[2*aj][2],   s[2*aj][3],   pl[1]);
            ph[2] = pack_split(s[2*aj+1][0], s[2*aj+1][1], pl[2]);
            ph[3] = pack_split(s[2*aj+1][2], s[2*aj+1][3], pl[3]);
            #pragma unroll
            for (int j = 0; j < 8; j++) {
                uint32_t voff = (uint32_t)(((aj * 16 + (lane & 7) + ((lane >> 3) & 1) * 8) * AP + j * 8) * 2);
                uint32_t vh[2], vl[2];
                ldsm_x2t(vh, sVh + voff);
                ldsm_x2t(vl, sVl + voff);
                mma16816(o[j], ph, vh);
                mma16816(o[j], ph, vl);
                mma16816(o[j], pl, vh);
            }
        }
        __syncthreads();
    }

    l0s += __shfl_xor_sync(0xffffffffu, l0s, 1);
    l0s += __shfl_xor_sync(0xffffffffu, l0s, 2);
    l1s += __shfl_xor_sync(0xffffffffu, l1s, 1);
    l1s += __shfl_xor_sync(0xffffffffu, l1s, 2);
    float i0 = 1.f / l0s, i1 = 1.f / l1s;

    const int row0 = q0 + w * 16 + er;
    #pragma unroll
    for (int j = 0; j < 8; j++) {
        int dim = j * 8 + ec;
        size_t o0 = (size_t)(b * Sq + row0) * Dm + h * HDc + dim;
        size_t o1 = (size_t)(b * Sq + row0 + 8) * Dm + h * HDc + dim;
        uint32_t lo;
        uint32_t hi = pack_split(o[j][0] * i0, o[j][1] * i0, lo);
        *(uint32_t*)&AH[o0] = hi; *(uint32_t*)&AL[o0] = lo;
        hi = pack_split(o[j][2] * i1, o[j][3] * i1, lo);
        *(uint32_t*)&AH[o1] = hi; *(uint32_t*)&AL[o1] = lo;
    }
}

// ---------------------------------------------------------------------------
extern "C" void kernel_launch(void* const* d_in, const int* in_sizes, int n_in,
                              void* d_out, int out_size)
{
    (void)in_sizes; (void)n_in; (void)out_size;
    const float* x  = (const float*)d_in[0];
    const float* WQ = (const float*)d_in[1];
    const float* WK = (const float*)d_in[2];
    const float* WV = (const float*)d_in[3];
    const float* WO = (const float*)d_in[4];
    float* out = (float*)d_out;

    __nv_bfloat16 *xh, *xl, *wh, *wl, *ah, *al;
    __nv_bfloat16 *qh, *ql, *kh, *kl, *vh, *vl;
    cudaGetSymbolAddress((void**)&xh, g_Xh);
    cudaGetSymbolAddress((void**)&xl, g_Xl);
    cudaGetSymbolAddress((void**)&wh, g_Wh);
    cudaGetSymbolAddress((void**)&wl, g_Wl);
    cudaGetSymbolAddress((void**)&ah, g_AH);
    cudaGetSymbolAddress((void**)&al, g_AL);
    cudaGetSymbolAddress((void**)&qh, g_Qh);
    cudaGetSymbolAddress((void**)&ql, g_Ql);
    cudaGetSymbolAddress((void**)&kh, g_Kh);
    cudaGetSymbolAddress((void**)&kl, g_Kl);
    cudaGetSymbolAddress((void**)&vh, g_Vh);
    cudaGetSymbolAddress((void**)&vl, g_Vl);

    static int attrs_set = 0;
    int gsmem = 2 * STAGEB;        // 81920
    int asmem = QB + 2 * STG;      // 92160
    if (!attrs_set) {
        cudaFuncSetAttribute(qkv_gemm, cudaFuncAttributeMaxDynamicSharedMemorySize, gsmem);
        cudaFuncSetAttribute(wo_gemm,  cudaFuncAttributeMaxDynamicSharedMemorySize, gsmem);
        cudaFuncSetAttribute(attn_mma, cudaFuncAttributeMaxDynamicSharedMemorySize, asmem);
        attrs_set = 1;
    }

    convx_k<<<Mtot * Dm / 4 / 256, 256>>>(x, xh, xl);
    const float* Ws[4] = {WQ, WK, WV, WO};
    for (int i = 0; i < 4; i++)
        convw_k<<<dim3(32, 32), dim3(32, 8)>>>(Ws[i], wh + (size_t)i * Dm * Dm,
                                               wl + (size_t)i * Dm * Dm);

    // fused QKV projection: N = 3072 (WQ|WK|WV contiguous in g_Wh/g_Wl)
    qkv_gemm<<<dim3(3 * Dm / 128, Mtot / 128), 256, gsmem>>>(
        xh, xl, wh, wl, qh, ql, kh, kl, vh, vl);

    attn_mma<<<dim3(Sq / 64, Hh, Bq), 128, asmem>>>(qh, ql, kh, kl, vh, vl, ah, al);

    wo_gemm<<<dim3(Dm / 128, Mtot / 128), 256, gsmem>>>(
        ah, al, wh + 3 * (size_t)Dm * Dm, wl + 3 * (size_t)Dm * Dm, out);
}